// round 15
// baseline (speedup 1.0000x reference)
#include <cuda_runtime.h>
#include <cuda_bf16.h>
#include <cstdint>
#include <cstddef>

// B=8, PH=PW=256, D=512, C=256, WS=8, NGRAM=2, HEADS=8, hd=32
// uni grid: 32x32 per image -> NPOS = 8*32*32 = 8192 positions
#define NPOS 8192

// Scratch (device globals; allocation is forbidden)
__device__ __align__(16) float g_wt[128 * 256];   // transposed conv weights [k][c]
__device__ __align__(16) float g_qkv[NPOS * 768]; // qkv per position [q|k|v] fp32
__device__ __align__(16) float g_biasf[512];      // fused bias

// bf16 split planes (hi/lo) for emulated-fp32 GEMM operands
__device__ __align__(16) __nv_bfloat16 g_uA_hi[NPOS * 256];  // uni (GEMM1 A)
__device__ __align__(16) __nv_bfloat16 g_uA_lo[NPOS * 256];
__device__ __align__(16) __nv_bfloat16 g_wq_hi[768 * 256];   // qkv_w (GEMM1 B)
__device__ __align__(16) __nv_bfloat16 g_wq_lo[768 * 256];
__device__ __align__(16) __nv_bfloat16 g_mf_hi[NPOS * 512];  // mfb (GEMM2 A)
__device__ __align__(16) __nv_bfloat16 g_mf_lo[NPOS * 512];
__device__ __align__(16) __nv_bfloat16 g_wc_hi[512 * 512];   // wcat (GEMM2 B)
__device__ __align__(16) __nv_bfloat16 g_wc_lo[512 * 512];

// ===========================================================================
// helpers
// ===========================================================================
__device__ __forceinline__ uint32_t smem_u32(const void* p) {
    uint32_t a;
    asm("{ .reg .u64 t; cvta.to.shared.u64 t, %1; cvt.u32.u64 %0, t; }"
        : "=r"(a) : "l"(p));
    return a;
}
__device__ __forceinline__ void cp_async16(uint32_t saddr, const void* g) {
    asm volatile("cp.async.cg.shared.global [%0], [%1], 16;" :: "r"(saddr), "l"(g));
}
__device__ __forceinline__ void cp_commit() {
    asm volatile("cp.async.commit_group;" ::: "memory");
}
__device__ __forceinline__ void cp_wait1() {
    asm volatile("cp.async.wait_group 1;" ::: "memory");
}
__device__ __forceinline__ void cp_wait0() {
    asm volatile("cp.async.wait_group 0;" ::: "memory");
}
// m16n8k16 bf16 MMA, fp32 accumulate
__device__ __forceinline__ void mma_bf16(float* c, const uint32_t* a, const uint32_t* b) {
    asm volatile(
        "mma.sync.aligned.m16n8k16.row.col.f32.bf16.bf16.f32 "
        "{%0,%1,%2,%3}, {%4,%5,%6,%7}, {%8,%9}, {%0,%1,%2,%3};"
        : "+f"(c[0]), "+f"(c[1]), "+f"(c[2]), "+f"(c[3])
        : "r"(a[0]), "r"(a[1]), "r"(a[2]), "r"(a[3]), "r"(b[0]), "r"(b[1]));
}
// ldmatrix: 4x (8x8 b16) tiles -> a0..a3 in mma order
__device__ __forceinline__ void ldsm_x4(uint32_t* r, uint32_t addr) {
    asm volatile("ldmatrix.sync.aligned.m8n8.x4.shared.b16 {%0,%1,%2,%3}, [%4];"
                 : "=r"(r[0]), "=r"(r[1]), "=r"(r[2]), "=r"(r[3]) : "r"(addr));
}
__device__ __forceinline__ void ldsm_x2(uint32_t* r, uint32_t addr) {
    asm volatile("ldmatrix.sync.aligned.m8n8.x2.shared.b16 {%0,%1}, [%2];"
                 : "=r"(r[0]), "=r"(r[1]) : "r"(addr));
}
__device__ __forceinline__ void split_bf16(float v, __nv_bfloat16* hi, __nv_bfloat16* lo) {
    __nv_bfloat16 h = __float2bfloat16(v);
    *hi = h;
    *lo = __float2bfloat16(v - __bfloat162float(h));
}

// ===========================================================================
// prep1: conv weight transpose + qkv_w bf16 split, merged.
// grid = 896: blocks [0,128) -> wtrans (32768 elems); [128,896) -> wq_split.
// ===========================================================================
__global__ void prep1_kernel(const float* __restrict__ uw,
                             const float* __restrict__ qkvw) {
    int blk = blockIdx.x;
    if (blk < 128) {
        int idx = blk * 256 + threadIdx.x;
        int c = idx >> 7;
        int kk = idx & 127;
        g_wt[kk * 256 + c] = uw[idx];
    } else {
        int idx = (blk - 128) * 256 + threadIdx.x;  // 768*256 elems
        split_bf16(qkvw[idx], &g_wq_hi[idx], &g_wq_lo[idx]);
    }
}

// ===========================================================================
// Depthwise conv 8x8 stride 8 (VALID). 8 w-positions per block. At the HBM
// roofline (89% DRAM, 1.07GB input) — do not touch.
// grid = 1024: blk = b*128 + h*4 + wg  (wg covers w = wg*8 .. wg*8+7)
// ===========================================================================
__global__ __launch_bounds__(256) void conv_kernel(const float* __restrict__ x,
                                                   const float* __restrict__ ub) {
    int blk = blockIdx.x;
    int bb = blk >> 7;
    int h = (blk >> 2) & 31;
    int wg = blk & 3;
    int c = threadIdx.x;

    const float* xp =
        x + ((size_t)(bb * 256 + h * 8) * 256 + wg * 64) * 512 + 2 * c;

    float acc[8];
#pragma unroll
    for (int p = 0; p < 8; p++) acc[p] = 0.f;

#pragma unroll
    for (int kh = 0; kh < 8; kh++) {
#pragma unroll
        for (int kw = 0; kw < 8; kw++) {
            int kidx = kh * 8 + kw;
            float w0 = g_wt[kidx * 256 + c];
            float w1 = g_wt[(64 + kidx) * 256 + c];
            const float* row = xp + ((size_t)kh * 256 + kw) * 512;
#pragma unroll
            for (int p = 0; p < 8; p++) {
                float2 xv = *(const float2*)(row + (size_t)p * 8 * 512);
                acc[p] += xv.x * w0 + xv.y * w1;
            }
        }
    }

    float b = ub[c];
    int pos0 = (bb * 32 + h) * 32 + wg * 8;
#pragma unroll
    for (int p = 0; p < 8; p++) {
        int o = (pos0 + p) * 256 + c;
        split_bf16(acc[p] + b, &g_uA_hi[o], &g_uA_lo[o]);
    }
}

// ===========================================================================
// Emulated-fp32 NT GEMM via bf16x2 split (3 MMAs: hi*hi + hi*lo + lo*hi):
//   C[m][n] = sum_k A[m][k]*B[n][k] + bias[n]
// 128x128 CTA tile, BK=32, double-buffered cp.async, 8 warps (2x4), 64x32/warp.
// SMEM: per buffer 4 planes (Ah,Al,Bh,Bl), each 128 rows x 40 bf16 pitch (80B).
// Fragments via ldmatrix. Requirements: M%128==0, N%128==0, K%32==0.
// ===========================================================================
#define PITCHB 80                       // bytes per row (64 data + 16 pad)
#define PLANE_B (128 * PITCHB)          // bytes per plane = 10240
#define BUF_B (4 * PLANE_B)             // bytes per buffer = 40960
#define TB_SMEM (2 * BUF_B)             // 81920 bytes

__global__ __launch_bounds__(256, 2) void bgemm_x2(const __nv_bfloat16* __restrict__ Ah,
                                                   const __nv_bfloat16* __restrict__ Al,
                                                   const __nv_bfloat16* __restrict__ Bh,
                                                   const __nv_bfloat16* __restrict__ Bl,
                                                   const float* __restrict__ bias,
                                                   float* __restrict__ C,
                                                   int K, int N) {
    extern __shared__ __align__(16) uint32_t smemw[];
    uint32_t sbase = smem_u32(smemw);

    int tid = threadIdx.x;
    int wid = tid >> 5;
    int lane = tid & 31;
    int g = lane >> 2;      // 0..7
    int tg = lane & 3;      // 0..3
    int warp_m = wid >> 2;  // 0..1
    int warp_n = wid & 3;   // 0..3

    int bm = blockIdx.y * 128;
    int bn = blockIdx.x * 128;

    // per-lane static ldmatrix offsets (bytes)
    uint32_t laneA =
        (uint32_t)((((lane & 7) + ((lane >> 3) & 1) * 8) * PITCHB) + ((lane >> 4) & 1) * 16);
    uint32_t laneB = (uint32_t)(((lane & 7) * PITCHB) + ((lane >> 3) & 1) * 16);

    // copy geometry: row = tid/2, half = tid&1 covers 16 bf16 (32B)
    int row = tid >> 1;
    int half = tid & 1;
    const __nv_bfloat16* gAh = Ah + (size_t)(bm + row) * K + half * 16;
    const __nv_bfloat16* gAl = Al + (size_t)(bm + row) * K + half * 16;
    const __nv_bfloat16* gBh = Bh + (size_t)(bn + row) * K + half * 16;
    const __nv_bfloat16* gBl = Bl + (size_t)(bn + row) * K + half * 16;
    uint32_t dst0 = sbase + (uint32_t)(row * PITCHB + half * 32);

    int nchunks = K >> 5;

#define LOAD_CHUNK(ci)                                                    \
    {                                                                     \
        uint32_t _o = ((ci) & 1) * BUF_B;                                 \
        int _k = (ci) * 32;                                               \
        cp_async16(dst0 + _o,                     gAh + _k);              \
        cp_async16(dst0 + _o + 16,                gAh + _k + 8);          \
        cp_async16(dst0 + _o + PLANE_B,           gAl + _k);              \
        cp_async16(dst0 + _o + PLANE_B + 16,      gAl + _k + 8);          \
        cp_async16(dst0 + _o + 2 * PLANE_B,       gBh + _k);              \
        cp_async16(dst0 + _o + 2 * PLANE_B + 16,  gBh + _k + 8);          \
        cp_async16(dst0 + _o + 3 * PLANE_B,       gBl + _k);              \
        cp_async16(dst0 + _o + 3 * PLANE_B + 16,  gBl + _k + 8);          \
        cp_commit();                                                      \
    }

    float c[4][4][4];
#pragma unroll
    for (int mt = 0; mt < 4; mt++)
#pragma unroll
        for (int nt = 0; nt < 4; nt++)
#pragma unroll
            for (int e = 0; e < 4; e++) c[mt][nt][e] = 0.f;

    LOAD_CHUNK(0);

    for (int i = 0; i < nchunks; i++) {
        if (i + 1 < nchunks) {
            LOAD_CHUNK(i + 1);
            cp_wait1();
        } else {
            cp_wait0();
        }
        __syncthreads();

        uint32_t bufb = sbase + (uint32_t)(i & 1) * BUF_B;
        uint32_t abase = bufb + (uint32_t)(warp_m * 64) * PITCHB + laneA;
        uint32_t bbase = bufb + 2 * PLANE_B + (uint32_t)(warp_n * 32) * PITCHB + laneB;

#pragma unroll
        for (int ks = 0; ks < 2; ks++) {
            uint32_t kb = (uint32_t)ks * 32;
            uint32_t bh[4][2], bl[4][2];
#pragma unroll
            for (int nt = 0; nt < 4; nt++) {
                uint32_t ba = bbase + (uint32_t)(nt * 8) * PITCHB + kb;
                ldsm_x2(bh[nt], ba);
                ldsm_x2(bl[nt], ba + PLANE_B);
            }
#pragma unroll
            for (int mt = 0; mt < 4; mt++) {
                uint32_t aa = abase + (uint32_t)(mt * 16) * PITCHB + kb;
                uint32_t ah[4], al[4];
                ldsm_x4(ah, aa);
                ldsm_x4(al, aa + PLANE_B);
#pragma unroll
                for (int nt = 0; nt < 4; nt++) {
                    mma_bf16(c[mt][nt], ah, bh[nt]);   // hi*hi
                    mma_bf16(c[mt][nt], ah, bl[nt]);   // hi*lo
                    mma_bf16(c[mt][nt], al, bh[nt]);   // lo*hi
                }
            }
        }
        __syncthreads();
    }
#undef LOAD_CHUNK

    // epilogue: direct stores with bias
#pragma unroll
    for (int nt = 0; nt < 4; nt++) {
        int col = bn + warp_n * 32 + nt * 8 + 2 * tg;
        float2 bv = *(const float2*)(bias + col);
#pragma unroll
        for (int mt = 0; mt < 4; mt++) {
            int r0 = bm + warp_m * 64 + mt * 16 + g;
            float2 v0 = make_float2(c[mt][nt][0] + bv.x, c[mt][nt][1] + bv.y);
            float2 v1 = make_float2(c[mt][nt][2] + bv.x, c[mt][nt][3] + bv.y);
            *(float2*)(C + (size_t)r0 * N + col) = v0;
            *(float2*)(C + (size_t)(r0 + 8) * N + col) = v1;
        }
    }
}

// ===========================================================================
// Attention over the 2x2 token window, both contexts, with token-mean.
// Writes bf16 hi/lo planes for GEMM2 A.
// ===========================================================================
__global__ __launch_bounds__(512) void attn_kernel(const float* __restrict__ table) {
    int p = blockIdx.x;
    int bb = p >> 10;
    int h = (p >> 5) & 31;
    int w = p & 31;
    int tid = threadIdx.x;
    int ctx = tid >> 8;
    int head = (tid >> 5) & 7;
    int lane = tid & 31;

    int rows[2], cols[2];
    if (ctx == 0) {
        rows[0] = h;
        rows[1] = (h == 31) ? 30 : h + 1;
        cols[0] = w;
        cols[1] = (w == 31) ? 30 : w + 1;
    } else {
        rows[0] = (h == 0) ? 1 : h - 1;
        rows[1] = h;
        cols[0] = (w == 0) ? 1 : w - 1;
        cols[1] = w;
    }

    float q[4], k[4], v[4];
#pragma unroll
    for (int n = 0; n < 4; n++) {
        int tp = (bb * 32 + rows[n >> 1]) * 32 + cols[n & 1];
        const float* base = g_qkv + (size_t)tp * 768 + head * 32 + lane;
        q[n] = base[0];
        k[n] = base[256];
        v[n] = base[512];
    }

    const float scale = 0.17677669529663687f;
    float s[4][4];
#pragma unroll
    for (int n = 0; n < 4; n++) {
#pragma unroll
        for (int m = 0; m < 4; m++) {
            float t = q[n] * k[m];
            t += __shfl_xor_sync(0xffffffffu, t, 16);
            t += __shfl_xor_sync(0xffffffffu, t, 8);
            t += __shfl_xor_sync(0xffffffffu, t, 4);
            t += __shfl_xor_sync(0xffffffffu, t, 2);
            t += __shfl_xor_sync(0xffffffffu, t, 1);
            int ridx = ((n >> 1) - (m >> 1) + 1) * 3 + ((n & 1) - (m & 1) + 1);
            s[n][m] = t * scale + table[ridx * 8 + head];
        }
    }

    float outd = 0.f;
#pragma unroll
    for (int n = 0; n < 4; n++) {
        float mx = fmaxf(fmaxf(s[n][0], s[n][1]), fmaxf(s[n][2], s[n][3]));
        float e0 = __expf(s[n][0] - mx);
        float e1 = __expf(s[n][1] - mx);
        float e2 = __expf(s[n][2] - mx);
        float e3 = __expf(s[n][3] - mx);
        float inv = 1.f / (e0 + e1 + e2 + e3);
        outd += (e0 * v[0] + e1 * v[1] + e2 * v[2] + e3 * v[3]) * inv;
    }
    int o = p * 512 + ctx * 256 + head * 32 + lane;
    split_bf16(outd * 0.25f, &g_mf_hi[o], &g_mf_lo[o]);
}

// ===========================================================================
// Fuse proj into merge; emit bf16 hi/lo planes for GEMM2 B.
// 2 d-rows per block (grid 256): halves pw L2 traffic, keeps >=148 blocks.
// ===========================================================================
__global__ __launch_bounds__(512) void fuse_w_kernel(const float* __restrict__ mw,
                                                     const float* __restrict__ pw) {
    int d0 = blockIdx.x * 2;
    int e = threadIdx.x;
    int eh = e & 255;
    int half = e >> 8;

    const float* m0 = mw + d0 * 512 + half * 256;
    const float* m1 = m0 + 512;
    float a0 = 0.f, a1 = 0.f;
#pragma unroll 4
    for (int cc = 0; cc < 256; cc++) {
        float v = pw[cc * 256 + eh];
        a0 += m0[cc] * v;
        a1 += m1[cc] * v;
    }
    split_bf16(a0, &g_wc_hi[d0 * 512 + e], &g_wc_lo[d0 * 512 + e]);
    split_bf16(a1, &g_wc_hi[(d0 + 1) * 512 + e], &g_wc_lo[(d0 + 1) * 512 + e]);
}

// One block per output d; 256 threads reduce over c.
__global__ __launch_bounds__(256) void fuse_bias_kernel(const float* __restrict__ mw,
                                                        const float* __restrict__ pb,
                                                        const float* __restrict__ mb) {
    __shared__ float red[8];
    int d = blockIdx.x;
    int t = threadIdx.x;
    float acc = pb[t] * (mw[d * 512 + t] + mw[d * 512 + 256 + t]);
    acc += __shfl_xor_sync(0xffffffffu, acc, 16);
    acc += __shfl_xor_sync(0xffffffffu, acc, 8);
    acc += __shfl_xor_sync(0xffffffffu, acc, 4);
    acc += __shfl_xor_sync(0xffffffffu, acc, 2);
    acc += __shfl_xor_sync(0xffffffffu, acc, 1);
    if ((t & 31) == 0) red[t >> 5] = acc;
    __syncthreads();
    if (t == 0) {
        float s = mb[d];
#pragma unroll
        for (int i = 0; i < 8; i++) s += red[i];
        g_biasf[d] = s;
    }
}

// ===========================================================================
// Launch. 4th launch = profiled slot = attn this round. Minimum chain
// prep1 -> conv -> GEMM1 -> attn fills slots 1-4 exactly.
// ===========================================================================
extern "C" void kernel_launch(void* const* d_in, const int* in_sizes, int n_in,
                              void* d_out, int out_size) {
    const float* x     = (const float*)d_in[0];
    const float* uw    = (const float*)d_in[1];
    const float* ub    = (const float*)d_in[2];
    const float* qkvw  = (const float*)d_in[3];
    const float* qkvb  = (const float*)d_in[4];
    const float* table = (const float*)d_in[5];
    const float* pw    = (const float*)d_in[6];
    const float* pb    = (const float*)d_in[7];
    const float* mw    = (const float*)d_in[8];
    const float* mb    = (const float*)d_in[9];
    float* out = (float*)d_out;

    float* qkv;
    float* biasf;
    __nv_bfloat16 *uAh, *uAl, *wqh, *wql, *mfh, *mfl, *wch, *wcl;
    cudaGetSymbolAddress((void**)&qkv, g_qkv);
    cudaGetSymbolAddress((void**)&biasf, g_biasf);
    cudaGetSymbolAddress((void**)&uAh, g_uA_hi);
    cudaGetSymbolAddress((void**)&uAl, g_uA_lo);
    cudaGetSymbolAddress((void**)&wqh, g_wq_hi);
    cudaGetSymbolAddress((void**)&wql, g_wq_lo);
    cudaGetSymbolAddress((void**)&mfh, g_mf_hi);
    cudaGetSymbolAddress((void**)&mfl, g_mf_lo);
    cudaGetSymbolAddress((void**)&wch, g_wc_hi);
    cudaGetSymbolAddress((void**)&wcl, g_wc_lo);

    cudaFuncSetAttribute(bgemm_x2, cudaFuncAttributeMaxDynamicSharedMemorySize,
                         TB_SMEM);

    // 1: merged prep (conv wtrans + qkv split)
    prep1_kernel<<<896, 256>>>(uw, qkvw);
    // 2: conv (HBM roofline)
    conv_kernel<<<1024, 256>>>(x, ub);
    // 3: GEMM1
    bgemm_x2<<<dim3(768 / 128, 8192 / 128), 256, TB_SMEM>>>(uAh, uAl, wqh, wql,
                                                            qkvb, qkv, 256, 768);
    // 4: attention  <-- profiled slot
    attn_kernel<<<8192, 512>>>(table);
    // 5,6: fused proj+merge weight/bias
    fuse_w_kernel<<<256, 512>>>(mw, pw);
    fuse_bias_kernel<<<512, 256>>>(mw, pb, mb);
    // 7: GEMM2
    bgemm_x2<<<dim3(512 / 128, 8192 / 128), 256, TB_SMEM>>>(mfh, mfl, wch, wcl,
                                                            biasf, out, 512, 512);
}

// round 16
// speedup vs baseline: 1.1349x; 1.1349x over previous
#include <cuda_runtime.h>
#include <cuda_bf16.h>
#include <cstdint>
#include <cstddef>

// B=8, PH=PW=256, D=512, C=256, WS=8, NGRAM=2, HEADS=8, hd=32
// uni grid: 32x32 per image -> NPOS = 8*32*32 = 8192 positions
#define NPOS 8192

// Scratch (device globals; allocation is forbidden)
__device__ __align__(16) float g_wt[128 * 256];   // transposed conv weights [k][c]
__device__ __align__(16) float g_qkv[NPOS * 768]; // qkv per position [q|k|v] fp32
__device__ __align__(16) float g_biasf[512];      // fused bias

// bf16 split planes (hi/lo) for emulated-fp32 GEMM operands
__device__ __align__(16) __nv_bfloat16 g_uA_hi[NPOS * 256];  // uni (GEMM1 A)
__device__ __align__(16) __nv_bfloat16 g_uA_lo[NPOS * 256];
__device__ __align__(16) __nv_bfloat16 g_wq_hi[768 * 256];   // qkv_w (GEMM1 B)
__device__ __align__(16) __nv_bfloat16 g_wq_lo[768 * 256];
__device__ __align__(16) __nv_bfloat16 g_mf_hi[NPOS * 512];  // mfb (GEMM2 A)
__device__ __align__(16) __nv_bfloat16 g_mf_lo[NPOS * 512];
__device__ __align__(16) __nv_bfloat16 g_wc_hi[512 * 512];   // wcat (GEMM2 B)
__device__ __align__(16) __nv_bfloat16 g_wc_lo[512 * 512];

// ===========================================================================
// helpers
// ===========================================================================
__device__ __forceinline__ uint32_t smem_u32(const void* p) {
    uint32_t a;
    asm("{ .reg .u64 t; cvta.to.shared.u64 t, %1; cvt.u32.u64 %0, t; }"
        : "=r"(a) : "l"(p));
    return a;
}
__device__ __forceinline__ void cp_async16(uint32_t saddr, const void* g) {
    asm volatile("cp.async.cg.shared.global [%0], [%1], 16;" :: "r"(saddr), "l"(g));
}
__device__ __forceinline__ void cp_commit() {
    asm volatile("cp.async.commit_group;" ::: "memory");
}
__device__ __forceinline__ void cp_wait1() {
    asm volatile("cp.async.wait_group 1;" ::: "memory");
}
__device__ __forceinline__ void cp_wait0() {
    asm volatile("cp.async.wait_group 0;" ::: "memory");
}
// m16n8k16 bf16 MMA, fp32 accumulate
__device__ __forceinline__ void mma_bf16(float* c, const uint32_t* a, const uint32_t* b) {
    asm volatile(
        "mma.sync.aligned.m16n8k16.row.col.f32.bf16.bf16.f32 "
        "{%0,%1,%2,%3}, {%4,%5,%6,%7}, {%8,%9}, {%0,%1,%2,%3};"
        : "+f"(c[0]), "+f"(c[1]), "+f"(c[2]), "+f"(c[3])
        : "r"(a[0]), "r"(a[1]), "r"(a[2]), "r"(a[3]), "r"(b[0]), "r"(b[1]));
}
// ldmatrix: 4x (8x8 b16) tiles -> a0..a3 in mma order
__device__ __forceinline__ void ldsm_x4(uint32_t* r, uint32_t addr) {
    asm volatile("ldmatrix.sync.aligned.m8n8.x4.shared.b16 {%0,%1,%2,%3}, [%4];"
                 : "=r"(r[0]), "=r"(r[1]), "=r"(r[2]), "=r"(r[3]) : "r"(addr));
}
__device__ __forceinline__ void ldsm_x2(uint32_t* r, uint32_t addr) {
    asm volatile("ldmatrix.sync.aligned.m8n8.x2.shared.b16 {%0,%1}, [%2];"
                 : "=r"(r[0]), "=r"(r[1]) : "r"(addr));
}
__device__ __forceinline__ void split_bf16(float v, __nv_bfloat16* hi, __nv_bfloat16* lo) {
    __nv_bfloat16 h = __float2bfloat16(v);
    *hi = h;
    *lo = __float2bfloat16(v - __bfloat162float(h));
}
__device__ __forceinline__ uint32_t pack_bf16x2(__nv_bfloat16 a, __nv_bfloat16 b) {
    uint16_t lo_u = *reinterpret_cast<uint16_t*>(&a);
    uint16_t hi_u = *reinterpret_cast<uint16_t*>(&b);
    return (uint32_t)lo_u | ((uint32_t)hi_u << 16);
}

// ===========================================================================
// prep1: conv weight transpose + qkv_w bf16 split, merged.
// grid = 896: blocks [0,128) -> wtrans (32768 elems); [128,896) -> wq_split.
// ===========================================================================
__global__ void prep1_kernel(const float* __restrict__ uw,
                             const float* __restrict__ qkvw) {
    int blk = blockIdx.x;
    if (blk < 128) {
        int idx = blk * 256 + threadIdx.x;
        int c = idx >> 7;
        int kk = idx & 127;
        g_wt[kk * 256 + c] = uw[idx];
    } else {
        int idx = (blk - 128) * 256 + threadIdx.x;  // 768*256 elems
        split_bf16(qkvw[idx], &g_wq_hi[idx], &g_wq_lo[idx]);
    }
}

// ===========================================================================
// Depthwise conv 8x8 stride 8 (VALID). 8 w-positions per block. At the HBM
// roofline (89% DRAM, 1.07GB input) — do not touch.
// ===========================================================================
__global__ __launch_bounds__(256) void conv_kernel(const float* __restrict__ x,
                                                   const float* __restrict__ ub) {
    int blk = blockIdx.x;
    int bb = blk >> 7;
    int h = (blk >> 2) & 31;
    int wg = blk & 3;
    int c = threadIdx.x;

    const float* xp =
        x + ((size_t)(bb * 256 + h * 8) * 256 + wg * 64) * 512 + 2 * c;

    float acc[8];
#pragma unroll
    for (int p = 0; p < 8; p++) acc[p] = 0.f;

#pragma unroll
    for (int kh = 0; kh < 8; kh++) {
#pragma unroll
        for (int kw = 0; kw < 8; kw++) {
            int kidx = kh * 8 + kw;
            float w0 = g_wt[kidx * 256 + c];
            float w1 = g_wt[(64 + kidx) * 256 + c];
            const float* row = xp + ((size_t)kh * 256 + kw) * 512;
#pragma unroll
            for (int p = 0; p < 8; p++) {
                float2 xv = *(const float2*)(row + (size_t)p * 8 * 512);
                acc[p] += xv.x * w0 + xv.y * w1;
            }
        }
    }

    float b = ub[c];
    int pos0 = (bb * 32 + h) * 32 + wg * 8;
#pragma unroll
    for (int p = 0; p < 8; p++) {
        int o = (pos0 + p) * 256 + c;
        split_bf16(acc[p] + b, &g_uA_hi[o], &g_uA_lo[o]);
    }
}

// ===========================================================================
// Emulated-fp32 NT GEMM via bf16x2 split (3 MMAs: hi*hi + hi*lo + lo*hi):
//   C[m][n] = sum_k A[m][k]*B[n][k] + bias[n]
// 128x128 CTA tile, BK=32, double-buffered cp.async, 8 warps (2x4), 64x32/warp.
// ===========================================================================
#define PITCHB 80                       // bytes per row (64 data + 16 pad)
#define PLANE_B (128 * PITCHB)          // bytes per plane = 10240
#define BUF_B (4 * PLANE_B)             // bytes per buffer = 40960
#define TB_SMEM (2 * BUF_B)             // 81920 bytes

__global__ __launch_bounds__(256, 2) void bgemm_x2(const __nv_bfloat16* __restrict__ Ah,
                                                   const __nv_bfloat16* __restrict__ Al,
                                                   const __nv_bfloat16* __restrict__ Bh,
                                                   const __nv_bfloat16* __restrict__ Bl,
                                                   const float* __restrict__ bias,
                                                   float* __restrict__ C,
                                                   int K, int N) {
    extern __shared__ __align__(16) uint32_t smemw[];
    uint32_t sbase = smem_u32(smemw);

    int tid = threadIdx.x;
    int wid = tid >> 5;
    int lane = tid & 31;
    int g = lane >> 2;      // 0..7
    int tg = lane & 3;      // 0..3
    int warp_m = wid >> 2;  // 0..1
    int warp_n = wid & 3;   // 0..3

    int bm = blockIdx.y * 128;
    int bn = blockIdx.x * 128;

    uint32_t laneA =
        (uint32_t)((((lane & 7) + ((lane >> 3) & 1) * 8) * PITCHB) + ((lane >> 4) & 1) * 16);
    uint32_t laneB = (uint32_t)(((lane & 7) * PITCHB) + ((lane >> 3) & 1) * 16);

    int row = tid >> 1;
    int half = tid & 1;
    const __nv_bfloat16* gAh = Ah + (size_t)(bm + row) * K + half * 16;
    const __nv_bfloat16* gAl = Al + (size_t)(bm + row) * K + half * 16;
    const __nv_bfloat16* gBh = Bh + (size_t)(bn + row) * K + half * 16;
    const __nv_bfloat16* gBl = Bl + (size_t)(bn + row) * K + half * 16;
    uint32_t dst0 = sbase + (uint32_t)(row * PITCHB + half * 32);

    int nchunks = K >> 5;

#define LOAD_CHUNK(ci)                                                    \
    {                                                                     \
        uint32_t _o = ((ci) & 1) * BUF_B;                                 \
        int _k = (ci) * 32;                                               \
        cp_async16(dst0 + _o,                     gAh + _k);              \
        cp_async16(dst0 + _o + 16,                gAh + _k + 8);          \
        cp_async16(dst0 + _o + PLANE_B,           gAl + _k);              \
        cp_async16(dst0 + _o + PLANE_B + 16,      gAl + _k + 8);          \
        cp_async16(dst0 + _o + 2 * PLANE_B,       gBh + _k);              \
        cp_async16(dst0 + _o + 2 * PLANE_B + 16,  gBh + _k + 8);          \
        cp_async16(dst0 + _o + 3 * PLANE_B,       gBl + _k);              \
        cp_async16(dst0 + _o + 3 * PLANE_B + 16,  gBl + _k + 8);          \
        cp_commit();                                                      \
    }

    float c[4][4][4];
#pragma unroll
    for (int mt = 0; mt < 4; mt++)
#pragma unroll
        for (int nt = 0; nt < 4; nt++)
#pragma unroll
            for (int e = 0; e < 4; e++) c[mt][nt][e] = 0.f;

    LOAD_CHUNK(0);

    for (int i = 0; i < nchunks; i++) {
        if (i + 1 < nchunks) {
            LOAD_CHUNK(i + 1);
            cp_wait1();
        } else {
            cp_wait0();
        }
        __syncthreads();

        uint32_t bufb = sbase + (uint32_t)(i & 1) * BUF_B;
        uint32_t abase = bufb + (uint32_t)(warp_m * 64) * PITCHB + laneA;
        uint32_t bbase = bufb + 2 * PLANE_B + (uint32_t)(warp_n * 32) * PITCHB + laneB;

#pragma unroll
        for (int ks = 0; ks < 2; ks++) {
            uint32_t kb = (uint32_t)ks * 32;
            uint32_t bh[4][2], bl[4][2];
#pragma unroll
            for (int nt = 0; nt < 4; nt++) {
                uint32_t ba = bbase + (uint32_t)(nt * 8) * PITCHB + kb;
                ldsm_x2(bh[nt], ba);
                ldsm_x2(bl[nt], ba + PLANE_B);
            }
#pragma unroll
            for (int mt = 0; mt < 4; mt++) {
                uint32_t aa = abase + (uint32_t)(mt * 16) * PITCHB + kb;
                uint32_t ah[4], al[4];
                ldsm_x4(ah, aa);
                ldsm_x4(al, aa + PLANE_B);
#pragma unroll
                for (int nt = 0; nt < 4; nt++) {
                    mma_bf16(c[mt][nt], ah, bh[nt]);   // hi*hi
                    mma_bf16(c[mt][nt], ah, bl[nt]);   // hi*lo
                    mma_bf16(c[mt][nt], al, bh[nt]);   // lo*hi
                }
            }
        }
        __syncthreads();
    }
#undef LOAD_CHUNK

    // epilogue: direct stores with bias
#pragma unroll
    for (int nt = 0; nt < 4; nt++) {
        int col = bn + warp_n * 32 + nt * 8 + 2 * tg;
        float2 bv = *(const float2*)(bias + col);
#pragma unroll
        for (int mt = 0; mt < 4; mt++) {
            int r0 = bm + warp_m * 64 + mt * 16 + g;
            float2 v0 = make_float2(c[mt][nt][0] + bv.x, c[mt][nt][1] + bv.y);
            float2 v1 = make_float2(c[mt][nt][2] + bv.x, c[mt][nt][3] + bv.y);
            *(float2*)(C + (size_t)r0 * N + col) = v0;
            *(float2*)(C + (size_t)(r0 + 8) * N + col) = v1;
        }
    }
}

// ===========================================================================
// Attention over the 2x2 token window, both contexts, with token-mean.
// 128 threads/block = 2 ctx x 8 heads x 8 lanes; 4 channels per thread
// via float4 loads. Dot-product reduction over 8 lanes (3 shfl).
// Writes bf16 hi/lo planes for GEMM2 A (packed 8B stores).
// ===========================================================================
__global__ __launch_bounds__(128) void attn_kernel(const float* __restrict__ table) {
    int p = blockIdx.x;
    int bb = p >> 10;
    int h = (p >> 5) & 31;
    int w = p & 31;
    int tid = threadIdx.x;
    int ctx = tid >> 6;           // 0..1
    int head = (tid >> 3) & 7;    // 0..7
    int ln = tid & 7;             // 0..7 (4 channels each)

    int rows[2], cols[2];
    if (ctx == 0) {
        rows[0] = h;
        rows[1] = (h == 31) ? 30 : h + 1;
        cols[0] = w;
        cols[1] = (w == 31) ? 30 : w + 1;
    } else {
        rows[0] = (h == 0) ? 1 : h - 1;
        rows[1] = h;
        cols[0] = (w == 0) ? 1 : w - 1;
        cols[1] = w;
    }

    float4 q[4], k[4], v[4];
#pragma unroll
    for (int n = 0; n < 4; n++) {
        int tp = (bb * 32 + rows[n >> 1]) * 32 + cols[n & 1];
        const float* base = g_qkv + (size_t)tp * 768 + head * 32 + ln * 4;
        q[n] = *(const float4*)(base);
        k[n] = *(const float4*)(base + 256);
        v[n] = *(const float4*)(base + 512);
    }

    const float scale = 0.17677669529663687f;
    float s[4][4];
#pragma unroll
    for (int n = 0; n < 4; n++) {
#pragma unroll
        for (int m = 0; m < 4; m++) {
            float t = q[n].x * k[m].x + q[n].y * k[m].y +
                      q[n].z * k[m].z + q[n].w * k[m].w;
            t += __shfl_xor_sync(0xffffffffu, t, 4);
            t += __shfl_xor_sync(0xffffffffu, t, 2);
            t += __shfl_xor_sync(0xffffffffu, t, 1);
            int ridx = ((n >> 1) - (m >> 1) + 1) * 3 + ((n & 1) - (m & 1) + 1);
            s[n][m] = t * scale + table[ridx * 8 + head];
        }
    }

    float4 outd = make_float4(0.f, 0.f, 0.f, 0.f);
#pragma unroll
    for (int n = 0; n < 4; n++) {
        float mx = fmaxf(fmaxf(s[n][0], s[n][1]), fmaxf(s[n][2], s[n][3]));
        float e0 = __expf(s[n][0] - mx);
        float e1 = __expf(s[n][1] - mx);
        float e2 = __expf(s[n][2] - mx);
        float e3 = __expf(s[n][3] - mx);
        float inv = 1.f / (e0 + e1 + e2 + e3);
        outd.x += (e0 * v[0].x + e1 * v[1].x + e2 * v[2].x + e3 * v[3].x) * inv;
        outd.y += (e0 * v[0].y + e1 * v[1].y + e2 * v[2].y + e3 * v[3].y) * inv;
        outd.z += (e0 * v[0].z + e1 * v[1].z + e2 * v[2].z + e3 * v[3].z) * inv;
        outd.w += (e0 * v[0].w + e1 * v[1].w + e2 * v[2].w + e3 * v[3].w) * inv;
    }
    outd.x *= 0.25f; outd.y *= 0.25f; outd.z *= 0.25f; outd.w *= 0.25f;

    // split + packed 8B stores (4 consecutive channels)
    __nv_bfloat16 h0, l0, h1, l1, h2, l2, h3, l3;
    split_bf16(outd.x, &h0, &l0);
    split_bf16(outd.y, &h1, &l1);
    split_bf16(outd.z, &h2, &l2);
    split_bf16(outd.w, &h3, &l3);
    int o = p * 512 + ctx * 256 + head * 32 + ln * 4;
    uint2 hp = make_uint2(pack_bf16x2(h0, h1), pack_bf16x2(h2, h3));
    uint2 lp = make_uint2(pack_bf16x2(l0, l1), pack_bf16x2(l2, l3));
    *(uint2*)(g_mf_hi + o) = hp;
    *(uint2*)(g_mf_lo + o) = lp;
}

// ===========================================================================
// Fuse proj into merge; emit bf16 hi/lo planes for GEMM2 B.
// 2 d-rows per block (grid 256).
// ===========================================================================
__global__ __launch_bounds__(512) void fuse_w_kernel(const float* __restrict__ mw,
                                                     const float* __restrict__ pw) {
    int d0 = blockIdx.x * 2;
    int e = threadIdx.x;
    int eh = e & 255;
    int half = e >> 8;

    const float* m0 = mw + d0 * 512 + half * 256;
    const float* m1 = m0 + 512;
    float a0 = 0.f, a1 = 0.f;
#pragma unroll 4
    for (int cc = 0; cc < 256; cc++) {
        float v = pw[cc * 256 + eh];
        a0 += m0[cc] * v;
        a1 += m1[cc] * v;
    }
    split_bf16(a0, &g_wc_hi[d0 * 512 + e], &g_wc_lo[d0 * 512 + e]);
    split_bf16(a1, &g_wc_hi[(d0 + 1) * 512 + e], &g_wc_lo[(d0 + 1) * 512 + e]);
}

// One block per output d; 256 threads reduce over c.
__global__ __launch_bounds__(256) void fuse_bias_kernel(const float* __restrict__ mw,
                                                        const float* __restrict__ pb,
                                                        const float* __restrict__ mb) {
    __shared__ float red[8];
    int d = blockIdx.x;
    int t = threadIdx.x;
    float acc = pb[t] * (mw[d * 512 + t] + mw[d * 512 + 256 + t]);
    acc += __shfl_xor_sync(0xffffffffu, acc, 16);
    acc += __shfl_xor_sync(0xffffffffu, acc, 8);
    acc += __shfl_xor_sync(0xffffffffu, acc, 4);
    acc += __shfl_xor_sync(0xffffffffu, acc, 2);
    acc += __shfl_xor_sync(0xffffffffu, acc, 1);
    if ((t & 31) == 0) red[t >> 5] = acc;
    __syncthreads();
    if (t == 0) {
        float s = mb[d];
#pragma unroll
        for (int i = 0; i < 8; i++) s += red[i];
        g_biasf[d] = s;
    }
}

// ===========================================================================
// Launch. 4th launch = profiled slot = attn (verify the restructure).
// ===========================================================================
extern "C" void kernel_launch(void* const* d_in, const int* in_sizes, int n_in,
                              void* d_out, int out_size) {
    const float* x     = (const float*)d_in[0];
    const float* uw    = (const float*)d_in[1];
    const float* ub    = (const float*)d_in[2];
    const float* qkvw  = (const float*)d_in[3];
    const float* qkvb  = (const float*)d_in[4];
    const float* table = (const float*)d_in[5];
    const float* pw    = (const float*)d_in[6];
    const float* pb    = (const float*)d_in[7];
    const float* mw    = (const float*)d_in[8];
    const float* mb    = (const float*)d_in[9];
    float* out = (float*)d_out;

    float* qkv;
    float* biasf;
    __nv_bfloat16 *uAh, *uAl, *wqh, *wql, *mfh, *mfl, *wch, *wcl;
    cudaGetSymbolAddress((void**)&qkv, g_qkv);
    cudaGetSymbolAddress((void**)&biasf, g_biasf);
    cudaGetSymbolAddress((void**)&uAh, g_uA_hi);
    cudaGetSymbolAddress((void**)&uAl, g_uA_lo);
    cudaGetSymbolAddress((void**)&wqh, g_wq_hi);
    cudaGetSymbolAddress((void**)&wql, g_wq_lo);
    cudaGetSymbolAddress((void**)&mfh, g_mf_hi);
    cudaGetSymbolAddress((void**)&mfl, g_mf_lo);
    cudaGetSymbolAddress((void**)&wch, g_wc_hi);
    cudaGetSymbolAddress((void**)&wcl, g_wc_lo);

    cudaFuncSetAttribute(bgemm_x2, cudaFuncAttributeMaxDynamicSharedMemorySize,
                         TB_SMEM);

    // 1: merged prep (conv wtrans + qkv split)
    prep1_kernel<<<896, 256>>>(uw, qkvw);
    // 2: conv (HBM roofline)
    conv_kernel<<<1024, 256>>>(x, ub);
    // 3: GEMM1
    bgemm_x2<<<dim3(768 / 128, 8192 / 128), 256, TB_SMEM>>>(uAh, uAl, wqh, wql,
                                                            qkvb, qkv, 256, 768);
    // 4: attention  <-- profiled slot
    attn_kernel<<<8192, 128>>>(table);
    // 5,6: fused proj+merge weight/bias
    fuse_w_kernel<<<256, 512>>>(mw, pw);
    fuse_bias_kernel<<<512, 256>>>(mw, pb, mb);
    // 7: GEMM2
    bgemm_x2<<<dim3(512 / 128, 8192 / 128), 256, TB_SMEM>>>(mfh, mfl, wch, wcl,
                                                            biasf, out, 512, 512);
}